// round 9
// baseline (speedup 1.0000x reference)
#include <cuda_runtime.h>
#include <cuda_bf16.h>

#define H      2048
#define E      64
#define NTOK   16384
#define TM     128
#define NBLK   128
#define NKT    32

typedef unsigned int u32;

// -------- device scratch (allocation-free) --------
__device__ __align__(16) unsigned char g_Wh[NKT * 8192];
__device__ __align__(16) unsigned char g_Wm[NKT * 8192];
__device__ float g_part_load[NBLK * E];
__device__ float g_part_z[NBLK];
__device__ unsigned int g_arrive = 0;

#define SWZ(o) ((o) ^ (((o) >> 3) & 0x70))
#define GAP_TH 4e-4f

__device__ __forceinline__ u32 smem_u32(const void* p) {
    u32 a;
    asm("{ .reg .u64 t; cvta.to.shared.u64 t, %1; cvt.u32.u64 %0, t; }" : "=r"(a) : "l"(p));
    return a;
}

#define CP16(dst, src) \
    asm volatile("cp.async.cg.shared.global [%0], [%1], 16;" :: "r"(dst), "l"(src) : "memory")
#define CP_COMMIT() asm volatile("cp.async.commit_group;" ::: "memory")
#define CP_WAIT0()  asm volatile("cp.async.wait_group 0;" ::: "memory")

#define LDSM4(r0, r1, r2, r3, addr) \
    asm volatile("ldmatrix.sync.aligned.m8n8.x4.shared.b16 {%0,%1,%2,%3}, [%4];" \
        : "=r"(r0), "=r"(r1), "=r"(r2), "=r"(r3) : "r"(addr))

#define MMA(d, a, b0, b1) \
    asm volatile("mma.sync.aligned.m16n8k16.row.col.f32.bf16.bf16.f32 " \
        "{%0,%1,%2,%3}, {%4,%5,%6,%7}, {%8,%9}, {%0,%1,%2,%3};" \
        : "+f"((d)[0]), "+f"((d)[1]), "+f"((d)[2]), "+f"((d)[3]) \
        : "r"((a)[0]), "r"((a)[1]), "r"((a)[2]), "r"((a)[3]), "r"(b0), "r"(b1))

// 2-limb bf16 split of a float pair (residual exact in fp32)
__device__ __forceinline__ void split2(float a, float b, u32& h, u32& m) {
    __nv_bfloat162 hb = __floats2bfloat162_rn(a, b);
    float2 hf = __bfloat1622float2(hb);
    __nv_bfloat162 mb = __floats2bfloat162_rn(a - hf.x, b - hf.y);
    h = *(u32*)&hb; m = *(u32*)&mb;
}

// -------- prep: split + pre-swizzle W --------
__global__ __launch_bounds__(256) void prep_kernel(const float* __restrict__ W) {
    int e = blockIdx.x;
    int t = threadIdx.x;
    int k0 = t * 8;
    int kt = k0 >> 6;
    int c  = k0 & 63;
    const float4* src = (const float4*)(W + (size_t)e * H + k0);
    float4 a = src[0], b = src[1];
    uint4 Hv, Mv;
    split2(a.x, a.y, Hv.x, Mv.x);
    split2(a.z, a.w, Hv.y, Mv.y);
    split2(b.x, b.y, Hv.z, Mv.z);
    split2(b.z, b.w, Hv.w, Mv.w);
    u32 off = kt * 8192 + SWZ((u32)(e * 128 + c * 2));
    *(uint4*)(g_Wh + off) = Hv;
    *(uint4*)(g_Wm + off) = Mv;
}

// one n-sweep: 8 MMAs over 8 distinct accumulators
__device__ __forceinline__ void pass8(float (*acc)[4], const u32* a, const u32* b) {
    #pragma unroll
    for (int g = 0; g < 4; g++) {
        MMA(acc[2*g],   a, b[4*g],   b[4*g+1]);
        MMA(acc[2*g+1], a, b[4*g+2], b[4*g+3]);
    }
}
__device__ __forceinline__ void ldsm_grp(u32* b, u32 base, int c, int rowpart, int kb16) {
    #pragma unroll
    for (int g = 0; g < 4; g++) {
        u32 off = (u32)((g * 16 + rowpart) * 128 + c * 32 + kb16);
        LDSM4(b[4*g], b[4*g+1], b[4*g+2], b[4*g+3], base + SWZ(off));
    }
}

// per-tile compute: 3 products (hh, mh, hm)
__device__ __forceinline__ void compute_tile(
    const float2* xq, u32 base, float (*acc)[4], int rowpart, int kb16)
{
    u32 bh[16], bm[16];
    ldsm_grp(bh, base, 0, rowpart, kb16);
    #pragma unroll
    for (int c = 0; c < 4; c++) {
        u32 ah[4], am[4];
        #pragma unroll
        for (int j = 0; j < 4; j++) {
            float2 p = xq[c * 4 + j];
            split2(p.x, p.y, ah[j], am[j]);
        }
        ldsm_grp(bm, base + 8192, c, rowpart, kb16);
        pass8(acc, ah, bh);
        pass8(acc, am, bh);
        if (c < 3) ldsm_grp(bh, base, c + 1, rowpart, kb16);
        pass8(acc, ah, bm);
    }
}

// load this lane's A-fragment source floats for one k-tile (16 float2)
__device__ __forceinline__ void load_x(
    const float* __restrict__ x, int rowBase, int w, int lane, int kt, float2* dst)
{
    const float* bl = x + (size_t)(rowBase + w * 16 + (lane >> 2)) * H + kt * 64 + (lane & 3) * 2;
    const float* bh = bl + 8 * H;
    #pragma unroll
    for (int c = 0; c < 4; c++) {
        dst[c*4+0] = *(const float2*)(bl + c * 16);
        dst[c*4+1] = *(const float2*)(bh + c * 16);
        dst[c*4+2] = *(const float2*)(bl + c * 16 + 8);
        dst[c*4+3] = *(const float2*)(bh + c * 16 + 8);
    }
}

// stage 2 pre-swizzled B splits for tile kt (16 KB)
__device__ __forceinline__ void stage_B(int kt, u32 smDst, int tid) {
    u32 d = smDst + tid * 32;
    const unsigned char* s;
    s = g_Wh + kt * 8192 + tid * 32; CP16(d, s);        CP16(d + 16, s + 16);
    s = g_Wm + kt * 8192 + tid * 32; CP16(d + 8192, s); CP16(d + 8192 + 16, s + 16);
}

__device__ __forceinline__ void token_epilogue(
    const float* lg, int lane, int tl, int rowBase, float* out, int out_size,
    float& z_accum, float* comb, int* flagcnt, int* flaglist)
{
    float m1 = -1e30f, m2 = -1e30f, m3 = -1e30f; int i1 = 0, i2 = 0;
    #pragma unroll
    for (int j = 0; j < 16; j++) {
        int e = (j >> 1) * 8 + (lane & 3) * 2 + (j & 1);
        float v = lg[j];
        if (v > m1)      { m3 = m2; m2 = m1; i2 = i1; m1 = v; i1 = e; }
        else if (v > m2) { m3 = m2; m2 = v; i2 = e; }
        else if (v > m3) { m3 = v; }
    }
    #pragma unroll
    for (int off = 1; off <= 2; off <<= 1) {
        float om1 = __shfl_xor_sync(0xFFFFFFFFu, m1, off);
        float om2 = __shfl_xor_sync(0xFFFFFFFFu, m2, off);
        float om3 = __shfl_xor_sync(0xFFFFFFFFu, m3, off);
        int   oi1 = __shfl_xor_sync(0xFFFFFFFFu, i1, off);
        int   oi2 = __shfl_xor_sync(0xFFFFFFFFu, i2, off);
        if (om1 > m1) {
            float n2; int j2; float n3;
            if (m1 > om2) { n2 = m1; j2 = i1; n3 = fmaxf(om2, m2); }
            else          { n2 = om2; j2 = oi2; n3 = fmaxf(m1, om3); }
            m1 = om1; i1 = oi1; m2 = n2; i2 = j2; m3 = n3;
        } else {
            if (om1 > m2) { m3 = fmaxf(m2, om2); m2 = om1; i2 = oi1; }
            else          { m3 = fmaxf(om1, m3); }
        }
    }
    float s = 0.0f, ex[16];
    #pragma unroll
    for (int j = 0; j < 16; j++) { ex[j] = __expf(lg[j] - m1); s += ex[j]; }
    s += __shfl_xor_sync(0xFFFFFFFFu, s, 1);
    s += __shfl_xor_sync(0xFFFFFFFFu, s, 2);
    float invS = 1.0f / s;
    #pragma unroll
    for (int j = 0; j < 16; j++) comb[j] += ex[j] * invS;
    if ((lane & 3) == 0) {
        float lse = m1 + __logf(s);
        z_accum += lse * lse;
        // softmax over the top-2 PROBABILITIES (p1 = 1/S, p2 = exp(m2-m1)/S)
        float p1 = invS, p2 = __expf(m2 - m1) * invS;
        float r2 = 1.0f / (1.0f + __expf(p1 - p2));
        float r1 = 1.0f - r2;
        int gt = rowBase + tl;
        if (2 * gt + 1 < out_size) { out[2 * gt] = r1; out[2 * gt + 1] = r2; }
        int ib = 2 * NTOK;
        if (ib + 2 * gt + 1 < out_size) {
            out[ib + 2 * gt] = (float)i1; out[ib + 2 * gt + 1] = (float)i2;
        }
        // near-tie -> exact recompute later
        if (m1 - m2 < GAP_TH || m2 - m3 < GAP_TH) {
            int slot = atomicAdd(flagcnt, 1);
            if (slot < 32) flaglist[slot] = tl;
        }
    }
}

__global__ __launch_bounds__(256, 1) void gate_kernel(
    const float* __restrict__ x, const float* __restrict__ Wg,
    float* __restrict__ out, int out_size)
{
    extern __shared__ __align__(128) unsigned char smc[];  // 2 x 16384 B buffers
    __shared__ float wsum[8][E];
    __shared__ float wz[8];
    __shared__ float redsm[256];
    __shared__ float zred2[4];
    __shared__ unsigned int lastflag;
    __shared__ int flagcnt;
    __shared__ int flaglist[32];

    const u32 smB = smem_u32(smc);
    const int tid = threadIdx.x;
    const int w = tid >> 5;
    const int lane = tid & 31;
    const int blk = blockIdx.x;
    const int rowBase = blk * TM;

    const int rowpart = ((lane >> 4) & 1) * 8 + (lane & 7);
    const int kb16    = ((lane >> 3) & 1) * 16;

    float acc[8][4];
    #pragma unroll
    for (int n = 0; n < 8; n++)
        #pragma unroll
        for (int j = 0; j < 4; j++) acc[n][j] = 0.0f;

    float2 xq0[16], xq1[16];

    if (tid == 0) flagcnt = 0;

    // prologue: stage tile 0
    stage_B(0, smB, tid);
    CP_COMMIT();
    load_x(x, rowBase, w, lane, 0, xq0);
    CP_WAIT0();
    __syncthreads();

    for (int kt = 0; kt < NKT; kt += 2) {
        stage_B(kt + 1, smB + 16384, tid);
        CP_COMMIT();
        load_x(x, rowBase, w, lane, kt + 1, xq1);

        compute_tile(xq0, smB, acc, rowpart, kb16);

        CP_WAIT0();
        __syncthreads();

        if (kt + 2 < NKT) {
            stage_B(kt + 2, smB, tid);
            CP_COMMIT();
            load_x(x, rowBase, w, lane, kt + 2, xq0);
        }

        compute_tile(xq1, smB + 16384, acc, rowpart, kb16);

        if (kt + 2 < NKT) {
            CP_WAIT0();
            __syncthreads();
        }
    }

    // -------- epilogue --------
    float lgl[16], lgh[16];
    #pragma unroll
    for (int n = 0; n < 8; n++) {
        lgl[2*n] = acc[n][0]; lgl[2*n+1] = acc[n][1];
        lgh[2*n] = acc[n][2]; lgh[2*n+1] = acc[n][3];
    }

    float comb[16];
    #pragma unroll
    for (int j = 0; j < 16; j++) comb[j] = 0.0f;
    float zacc = 0.0f;

    int tl_lo = w * 16 + (lane >> 2);
    token_epilogue(lgl, lane, tl_lo,     rowBase, out, out_size, zacc, comb, &flagcnt, flaglist);
    token_epilogue(lgh, lane, tl_lo + 8, rowBase, out, out_size, zacc, comb, &flagcnt, flaglist);

    // warp reduce expert prob sums across quads (tokens)
    #pragma unroll
    for (int off = 4; off <= 16; off <<= 1)
        #pragma unroll
        for (int j = 0; j < 16; j++)
            comb[j] += __shfl_down_sync(0xFFFFFFFFu, comb[j], off);
    if (lane < 4) {
        #pragma unroll
        for (int j = 0; j < 16; j++)
            wsum[w][(j >> 1) * 8 + lane * 2 + (j & 1)] = comb[j];
    }
    float zs = zacc;
    #pragma unroll
    for (int off = 16; off > 0; off >>= 1)
        zs += __shfl_down_sync(0xFFFFFFFFu, zs, off);
    if (lane == 0) wz[w] = zs;
    __syncthreads();

    // -------- exact fp32 recompute for near-tie tokens --------
    {
        int nf = flagcnt; if (nf > 32) nf = 32;
        for (int f = 0; f < nf; f++) {
            int tl = flaglist[f];
            int gt = rowBase + tl;
            const float4* xr4 = (const float4*)(x + (size_t)gt * H);
            const float4* wr4 = (const float4*)(Wg + (size_t)(tid & 63) * H);
            int q = tid >> 6;
            float s0 = 0.f, s1 = 0.f, s2 = 0.f, s3 = 0.f;
            #pragma unroll 4
            for (int k = q * 128; k < q * 128 + 128; k++) {
                float4 xv = xr4[k], wv = wr4[k];
                s0 += xv.x * wv.x; s1 += xv.y * wv.y;
                s2 += xv.z * wv.z; s3 += xv.w * wv.w;
            }
            redsm[tid] = (s0 + s1) + (s2 + s3);
            __syncthreads();
            if (tid == 0) {
                float m1 = -1e30f, m2 = -1e30f; int i1 = 0, i2 = 0;
                float lg[64];
                for (int e = 0; e < E; e++) {
                    float v = redsm[e] + redsm[64 + e] + redsm[128 + e] + redsm[192 + e];
                    lg[e] = v;
                    if (v > m1) { m2 = m1; i2 = i1; m1 = v; i1 = e; }
                    else if (v > m2) { m2 = v; i2 = e; }
                }
                float s = 0.0f;
                for (int e = 0; e < E; e++) s += __expf(lg[e] - m1);
                float inv = 1.0f / s;
                float p1 = inv, p2 = __expf(m2 - m1) * inv;
                float r2 = 1.0f / (1.0f + __expf(p1 - p2));
                float r1 = 1.0f - r2;
                if (2 * gt + 1 < out_size) { out[2 * gt] = r1; out[2 * gt + 1] = r2; }
                int ib = 2 * NTOK;
                if (ib + 2 * gt + 1 < out_size) {
                    out[ib + 2 * gt] = (float)i1; out[ib + 2 * gt + 1] = (float)i2;
                }
            }
            __syncthreads();
        }
    }

    if (tid < E) {
        float s = 0.0f;
        #pragma unroll
        for (int ww = 0; ww < 8; ww++) s += wsum[ww][tid];
        g_part_load[blk * E + tid] = s;
    }
    if (tid == 0) {
        float z = 0.0f;
        #pragma unroll
        for (int ww = 0; ww < 8; ww++) z += wz[ww];
        g_part_z[blk] = z;
    }

    // -------- last-block loss reduction --------
    __threadfence();
    __syncthreads();
    if (tid == 0) {
        unsigned int v = atomicAdd(&g_arrive, 1u);
        lastflag = (v == NBLK - 1) ? 1u : 0u;
    }
    __syncthreads();
    if (lastflag) {
        __threadfence();
        int qq = tid >> 6, e = tid & 63;
        float sacc = 0.0f;
        for (int b = qq * 32; b < qq * 32 + 32; b++) sacc += g_part_load[b * E + e];
        redsm[tid] = sacc;
        __syncthreads();
        if (tid < E) {
            float S = redsm[tid] + redsm[64 + tid] + redsm[128 + tid] + redsm[192 + tid];
            float d = S * (1.0f / (float)NTOK) - (1.0f / (float)E);
            redsm[tid] = d * d;
        }
        __syncthreads();
        if (tid < 32) {
            float v = redsm[tid] + redsm[tid + 32];
            #pragma unroll
            for (int o = 16; o > 0; o >>= 1) v += __shfl_down_sync(0xFFFFFFFFu, v, o);
            if (tid == 0) redsm[0] = v;  // lb sum
        }
        if (tid >= 128 && tid < 256) {
            float zv = g_part_z[tid - 128];
            #pragma unroll
            for (int o = 16; o > 0; o >>= 1) zv += __shfl_down_sync(0xFFFFFFFFu, zv, o);
            if (((tid - 128) & 31) == 0) zred2[(tid - 128) >> 5] = zv;
        }
        __syncthreads();
        if (tid == 0) {
            float z = zred2[0] + zred2[1] + zred2[2] + zred2[3];
            float total = 0.01f * redsm[0] + 1e-4f * (z / (float)NTOK);
            if (out_size > 4 * NTOK) out[4 * NTOK] = total;
            g_arrive = 0;
        }
    }
}

extern "C" void kernel_launch(void* const* d_in, const int* in_sizes, int n_in,
                              void* d_out, int out_size)
{
    const float* x = (const float*)d_in[0];
    const float* W = (const float*)d_in[1];
    float* out = (float*)d_out;

    cudaFuncSetAttribute(gate_kernel, cudaFuncAttributeMaxDynamicSharedMemorySize, 32768);
    prep_kernel<<<E, 256>>>(W);
    gate_kernel<<<NBLK, 256, 32768>>>(x, W, out, out_size);
}